// round 4
// baseline (speedup 1.0000x reference)
#include <cuda_runtime.h>
#include <stdint.h>

// StationSelectionAggregator:
//   schedule: [B, WIN, N_ST]  one-hot float32
//   csi:      [B, N_ST, N_SUB, WIN] float32
//   out:      [B, WIN, N_SUB] float32
//   out[b,w,s] = csi[b, t(b,w), s, w]  (exact selection; schedule one-hot).
//
// DRAM bytes are floored (~589 MB measured, all variants). Purely a
// bandwidth-achievement problem. Lessons: NO streaming cache hints (cost 5%
// in R2/R3); R1's 32x32 gather-transpose structure achieved best BW.
// This round: persistent grid-stride CTAs to software-pipeline LDGs across
// tile iterations and remove wave-transition / CTA-drain bubbles.
#define B_     32
#define NST    8
#define NSUB   256
#define WIN    2048
#define NTILES (B_ * (NSUB / 32) * (WIN / 32))   // 32*8*64 = 16384
#define GRID   1184                              // 148 SMs * 8 resident CTAs

__global__ __launch_bounds__(256)
void station_select_kernel(const float* __restrict__ sched,
                           const float* __restrict__ csi,
                           float* __restrict__ out) {
    __shared__ float tile[32][33];   // [s_local][w_local], +1 pad

    const int tid = threadIdx.x;     // 0..255
    const int tx  = tid & 31;
    const int ty  = tid >> 5;        // 0..7

    for (int tileId = blockIdx.x; tileId < NTILES; tileId += GRID) {
        // tile decode: w fastest -> concurrent CTAs cover contiguous lines
        const int wT   = tileId & 63;          // 64 w tiles
        const int rest = tileId >> 6;
        const int sT   = rest & 7;             // 8 s tiles
        const int b    = rest >> 3;            // batch
        const int w0   = wT * 32;
        const int s0   = sT * 32;

        // --- station index for w0+tx (exact: one-hot is 0.0/1.0) ---
        // redundant across the 8 warps but L1-resident; no smem, no barrier.
        const float4* sp = reinterpret_cast<const float4*>(
            sched + ((size_t)b * WIN + (size_t)(w0 + tx)) * NST);
        const float4 a = __ldg(sp);
        const float4 c = __ldg(sp + 1);
        const float tf = a.y + 2.f * a.z + 3.f * a.w +
                         4.f * c.x + 5.f * c.y + 6.f * c.z + 7.f * c.w;
        const int t = (int)(tf + 0.5f);

        // --- issue gather loads BEFORE the barrier: they overlap the
        //     previous iteration's smem-read/store phase ---
        const float* p = csi
            + ((size_t)(b * NST + t) * NSUB + (size_t)s0) * WIN
            + (size_t)(w0 + tx);
        float v[4];
#pragma unroll
        for (int r = 0; r < 4; r++)
            v[r] = p[(size_t)(ty + r * 8) * WIN];

        __syncthreads();   // prior iteration finished reading tile[][]

#pragma unroll
        for (int r = 0; r < 4; r++)
            tile[ty + r * 8][tx] = v[r];       // bank (sl+tx)&31: conflict-free

        __syncthreads();

        // --- transposed coalesced writes along s ---
#pragma unroll
        for (int r = 0; r < 4; r++) {
            const int wl = ty + r * 8;
            out[((size_t)b * WIN + (size_t)(w0 + wl)) * NSUB + (size_t)(s0 + tx)]
                = tile[tx][wl];                // bank (tx+wl)&31: conflict-free
        }
    }
}

extern "C" void kernel_launch(void* const* d_in, const int* in_sizes, int n_in,
                              void* d_out, int out_size) {
    const float* sched = (const float*)d_in[0];
    const float* csi   = (const float*)d_in[1];
    if (n_in >= 2 && in_sizes[0] != 524288) {   // schedule = 32*2048*8 elems
        sched = (const float*)d_in[1];
        csi   = (const float*)d_in[0];
    }
    float* out = (float*)d_out;

    station_select_kernel<<<GRID, 256>>>(sched, csi, out);
}

// round 6
// speedup vs baseline: 1.0632x; 1.0632x over previous
#include <cuda_runtime.h>
#include <stdint.h>

// StationSelectionAggregator:
//   schedule: [B, WIN, N_ST]  one-hot float32
//   csi:      [B, N_ST, N_SUB, WIN] float32
//   out:      [B, WIN, N_SUB] float32
//   out[b,w,s] = csi[b, t(b,w), s, w]  (exact selection; schedule one-hot).
//
// DRAM bytes floored at ~589 MB -> pure bandwidth-achievement race.
// R5 fix: stride-33 smem rows are NOT 16B aligned; do 4 scalar LDS and
// assemble the float4 in registers for STG.128 (conflict-free verified).
#define B_    32
#define NST   8
#define NSUB  256
#define WIN   2048

__global__ __launch_bounds__(256)
void station_select_kernel(const float* __restrict__ sched,
                           const float* __restrict__ csi,
                           float* __restrict__ out) {
    // blockIdx.x : w tile (WIN/64 = 32)  [fastest -> contiguous lines across CTAs]
    // blockIdx.y : s tile (NSUB/32 = 8)
    // blockIdx.z : batch  (32)
    __shared__ float tile[64][33];   // [w_local][s_local], +1 pad
    __shared__ int   tw[64];         // selected station per w in this tile

    const int b   = blockIdx.z;
    const int w0  = blockIdx.x * 64;
    const int s0  = blockIdx.y * 32;
    const int tid = threadIdx.x;     // 0..255
    const int tx  = tid & 31;
    const int ty  = tid >> 5;        // warp id 0..7

    // --- station index per w (exact: one-hot values are 0.0/1.0) ---
    if (tid < 64) {
        const float4* sp = reinterpret_cast<const float4*>(
            sched + ((size_t)b * WIN + (size_t)(w0 + tid)) * NST);
        const float4 a = sp[0];
        const float4 c = sp[1];
        const float tf = a.y + 2.f * a.z + 3.f * a.w +
                         4.f * c.x + 5.f * c.y + 6.f * c.z + 7.f * c.w;
        tw[tid] = (int)(tf + 0.5f);
    }
    __syncthreads();

    // --- gather: coalesced along w; 8 independent loads batched per thread ---
    const int t0 = tw[tx];           // station for w0 + tx
    const int t1 = tw[32 + tx];      // station for w0 + 32 + tx
    const float* p0 = csi + ((size_t)(b * NST + t0) * NSUB + (size_t)s0) * WIN
                          + (size_t)(w0 + tx);
    const float* p1 = csi + ((size_t)(b * NST + t1) * NSUB + (size_t)s0) * WIN
                          + (size_t)(w0 + 32 + tx);

    float v0[4], v1[4];
#pragma unroll
    for (int r = 0; r < 4; r++) v0[r] = p0[(size_t)(ty + r * 8) * WIN];
#pragma unroll
    for (int r = 0; r < 4; r++) v1[r] = p1[(size_t)(ty + r * 8) * WIN];

    // smem writes: bank = (33*tx + sl)&31 = (tx + sl)&31 -> conflict-free
#pragma unroll
    for (int r = 0; r < 4; r++) tile[tx][ty + r * 8]      = v0[r];
#pragma unroll
    for (int r = 0; r < 4; r++) tile[32 + tx][ty + r * 8] = v1[r];
    __syncthreads();

    // --- store: 4 scalar LDS -> STG.128, coalesced along s ---
    // lane -> (row wl, quad q): banks (wl + 4q + i) mod 32 all distinct per warp
    const int q  = tx & 7;           // float4 index along s
    const int wr = tx >> 3;          // 0..3 row within warp
#pragma unroll
    for (int h = 0; h < 2; h++) {
        const int wl = h * 32 + ty * 4 + wr;     // 0..63
        float4 val;
        val.x = tile[wl][4 * q + 0];
        val.y = tile[wl][4 * q + 1];
        val.z = tile[wl][4 * q + 2];
        val.w = tile[wl][4 * q + 3];
        *reinterpret_cast<float4*>(
            out + ((size_t)b * WIN + (size_t)(w0 + wl)) * NSUB + (size_t)(s0 + 4 * q))
            = val;
    }
}

extern "C" void kernel_launch(void* const* d_in, const int* in_sizes, int n_in,
                              void* d_out, int out_size) {
    const float* sched = (const float*)d_in[0];
    const float* csi   = (const float*)d_in[1];
    if (n_in >= 2 && in_sizes[0] != 524288) {   // schedule = 32*2048*8 elems
        sched = (const float*)d_in[1];
        csi   = (const float*)d_in[0];
    }
    float* out = (float*)d_out;

    dim3 block(256, 1, 1);
    dim3 grid(WIN / 64, NSUB / 32, B_);
    station_select_kernel<<<grid, block>>>(sched, csi, out);
}